// round 10
// baseline (speedup 1.0000x reference)
#include <cuda_runtime.h>
#include <cuda_bf16.h>
#include <cuda_fp16.h>
#include <cstdint>
#include <cstddef>

// ---------------------------------------------------------------------------
// SparseGraphLearn:
//   h = inputs @ weight          [M=100000,256] @ [256,128]  fp32
//   edge_weight = relu(|h[e0]-h[e1]| @ a)   [E]
// d_out = [ h | edge_weight ]
//
// GEMM: mma.sync m16n8k16 bf16, truncation 2-term split (3 cross products).
//   Pipelined: B (both splits) fully smem-resident, A double-buffered with
//   conversion interleaved between MMA k-steps. 1 CTA/SM by design.
// Edge: gathers from fp16 shadow of h.
// ---------------------------------------------------------------------------

#define KTOT 256
#define NTOT 128
#define MTILE 128
#define KCH 64
#define LDS_W 36          // A row stride in words (4 mod 32 -> conflict-free)
#define B_W   132         // B row stride in words (256 bf16 + pad, 4 mod 32)
#define NMAX 100000

// smem layout (bytes)
#define S_BHI  0
#define S_BMI  67584                  // 128*132*4
#define S_A0   135168                 // A buffers: [buf][hi|mid]
#define A_BUF_BYTES 36864             // hi(18432) + mid(18432)
#define A_MID_OFF   18432
#define S_TOTAL (135168 + 2*A_BUF_BYTES)   // 208896

__device__ __nv_bfloat16 g_whi[NTOT * KTOT];   // [n][k]
__device__ __nv_bfloat16 g_wmid[NTOT * KTOT];
__device__ __half        g_h16[(size_t)NMAX * NTOT];

__device__ __forceinline__ void mma_bf16(float* d, const uint32_t* a, const uint32_t* b) {
    asm volatile(
        "mma.sync.aligned.m16n8k16.row.col.f32.bf16.bf16.f32 "
        "{%0,%1,%2,%3}, {%4,%5,%6,%7}, {%8,%9}, {%0,%1,%2,%3};"
        : "+f"(d[0]), "+f"(d[1]), "+f"(d[2]), "+f"(d[3])
        : "r"(a[0]), "r"(a[1]), "r"(a[2]), "r"(a[3]), "r"(b[0]), "r"(b[1]));
}

__device__ __forceinline__ void ldsm4(uint32_t* r, uint32_t addr) {
    asm volatile("ldmatrix.sync.aligned.m8n8.x4.shared.b16 {%0,%1,%2,%3}, [%4];"
        : "=r"(r[0]), "=r"(r[1]), "=r"(r[2]), "=r"(r[3]) : "r"(addr));
}

// Split two fp32 -> (hi bf16x2 via truncation, mid bf16x2 rn).
__device__ __forceinline__ void split2(float x, float y,
                                       uint32_t& hi, uint32_t& mid) {
    uint32_t ux = __float_as_uint(x), uy = __float_as_uint(y);
    hi = __byte_perm(ux, uy, 0x7632);
    float fx = x - __uint_as_float(ux & 0xFFFF0000u);
    float fy = y - __uint_as_float(uy & 0xFFFF0000u);
    __nv_bfloat162 m = __floats2bfloat162_rn(fx, fy);
    mid = *(uint32_t*)&m;
}

__global__ __launch_bounds__(256) void prep_w(const float* __restrict__ W) {
    int idx = blockIdx.x * 256 + threadIdx.x;   // 32768
    int k = idx >> 7;
    int n = idx & 127;
    float x = W[idx];
    uint32_t ux = __float_as_uint(x);
    float mid = x - __uint_as_float(ux & 0xFFFF0000u);
    g_whi [n * KTOT + k] = __ushort_as_bfloat16((unsigned short)(ux >> 16));
    g_wmid[n * KTOT + k] = __float2bfloat16(mid);
}

__global__ __launch_bounds__(512, 1) void sgl_gemm_mma(
    const float* __restrict__ A,   // [M, 256]
    float* __restrict__ H,         // [M, 128]
    int M)
{
    extern __shared__ char smem[];
    const uint32_t sbase = (uint32_t)__cvta_generic_to_shared(smem);
    uint32_t* sB0 = (uint32_t*)(smem + S_BHI);
    uint32_t* sB1 = (uint32_t*)(smem + S_BMI);

    const int tid  = threadIdx.x;
    const int wid  = tid >> 5;
    const int lane = tid & 31;
    const int g    = lane >> 2;
    const int t    = lane & 3;
    const int m0w  = (wid >> 2) * 32;
    const int n0w  = (wid & 3) * 32;
    const int row0 = blockIdx.x * MTILE;

    // ldmatrix lane mappings (byte offsets, used ONLY with shared-space asm)
    const int aRow  = (lane & 7) + ((lane >> 3) & 1) * 8;
    const int aKw   = (lane >> 4) * 4;
    const int baseA0 = ((m0w + aRow) * LDS_W + aKw) * 4;
    const int baseA1 = ((m0w + 16 + aRow) * LDS_W + aKw) * 4;
    const int bRow  = lane & 7;
    const int bNt   = lane >> 4;
    const int bKw   = ((lane >> 3) & 1) * 4;
    const int baseB0 = ((n0w + (0 + bNt) * 8 + bRow) * B_W + bKw) * 4;
    const int baseB1 = ((n0w + (2 + bNt) * 8 + bRow) * B_W + bKw) * 4;

    float acc[2][4][4];
#pragma unroll
    for (int mt = 0; mt < 2; ++mt)
#pragma unroll
        for (int nt = 0; nt < 4; ++nt)
#pragma unroll
            for (int j = 0; j < 4; ++j) acc[mt][nt][j] = 0.f;

    const int ar = tid >> 2;
    const int at = tid & 3;
    const bool arok = (row0 + ar) < M;
    const float4* arow = (const float4*)(A + (size_t)(row0 + ar) * KTOT);
    const int aw0base = ar * LDS_W + at * 8;   // word offset of thread's strip

    // ---- prologue: resident B load (both splits) ----
    {
        const uint2* src_hi = (const uint2*)g_whi;
        const uint2* src_mi = (const uint2*)g_wmid;
#pragma unroll
        for (int s = 0; s < 16; ++s) {
            int idx = tid + s * 512;     // 0..8191
            int n = idx >> 6;
            int q = idx & 63;
            *(uint2*)(sB0 + n * B_W + q * 2) = src_hi[n * 64 + q];
            *(uint2*)(sB1 + n * B_W + q * 2) = src_mi[n * 64 + q];
        }
    }

    float4 v[4];
    // convert chunk 0 into buffer 0 (generic pointers for stores)
#pragma unroll
    for (int j = 0; j < 4; ++j)
        v[j] = arok ? arow[at * 4 + j] : make_float4(0.f, 0.f, 0.f, 0.f);
    {
        uint32_t* dsthi = (uint32_t*)(smem + S_A0);
        uint32_t* dstmi = (uint32_t*)(smem + S_A0 + A_MID_OFF);
#pragma unroll
        for (int j = 0; j < 4; ++j) {
            uint32_t h0, mm0, h1, mm1;
            split2(v[j].x, v[j].y, h0, mm0);
            split2(v[j].z, v[j].w, h1, mm1);
            *(uint2*)(dsthi + aw0base + j * 2) = make_uint2(h0, h1);
            *(uint2*)(dstmi + aw0base + j * 2) = make_uint2(mm0, mm1);
        }
    }
    // prefetch chunk 1
#pragma unroll
    for (int j = 0; j < 4; ++j)
        v[j] = arok ? arow[16 + at * 4 + j] : make_float4(0.f, 0.f, 0.f, 0.f);
    __syncthreads();

    // ---- main pipelined loop ----
#pragma unroll
    for (int ch = 0; ch < 4; ++ch) {
        const uint32_t abCur = sbase + S_A0 + (ch & 1) * A_BUF_BYTES;        // asm only
        char* abNxtP = smem + S_A0 + ((ch + 1) & 1) * A_BUF_BYTES;            // generic

#pragma unroll
        for (int ks = 0; ks < 4; ++ks) {
            const int kwA = ks * 32;
            const int kwB = (ch * 4 + ks) * 32;

            uint32_t afr[2][2][4];
            ldsm4(afr[0][0], abCur + baseA0 + kwA);
            ldsm4(afr[0][1], abCur + baseA1 + kwA);
            ldsm4(afr[1][0], abCur + A_MID_OFF + baseA0 + kwA);
            ldsm4(afr[1][1], abCur + A_MID_OFF + baseA1 + kwA);

            uint32_t bfr[2][8];
            ldsm4(&bfr[0][0], sbase + S_BHI + baseB0 + kwB);
            ldsm4(&bfr[0][4], sbase + S_BHI + baseB1 + kwB);
            ldsm4(&bfr[1][0], sbase + S_BMI + baseB0 + kwB);
            ldsm4(&bfr[1][4], sbase + S_BMI + baseB1 + kwB);

#pragma unroll
            for (int mt = 0; mt < 2; ++mt)
#pragma unroll
                for (int nt = 0; nt < 4; ++nt) {
                    mma_bf16(acc[mt][nt], afr[0][mt], &bfr[0][nt * 2]);  // hi*hi
                    mma_bf16(acc[mt][nt], afr[0][mt], &bfr[1][nt * 2]);  // hi*mid
                    mma_bf16(acc[mt][nt], afr[1][mt], &bfr[0][nt * 2]);  // mid*hi
                }

            // interleaved convert of next chunk (generic-pointer stores)
            if (ch < 3) {
                uint32_t h0, mm0, h1, mm1;
                split2(v[ks].x, v[ks].y, h0, mm0);
                split2(v[ks].z, v[ks].w, h1, mm1);
                *(uint2*)(abNxtP + (aw0base + ks * 2) * 4) = make_uint2(h0, h1);
                *(uint2*)(abNxtP + A_MID_OFF + (aw0base + ks * 2) * 4) = make_uint2(mm0, mm1);
            }
        }

        // prefetch chunk ch+2 (consumed by next iteration's converts)
        if (ch < 2) {
            const float4* src = arow + (ch + 2) * 16 + at * 4;
#pragma unroll
            for (int j = 0; j < 4; ++j)
                v[j] = arok ? src[j] : make_float4(0.f, 0.f, 0.f, 0.f);
        }
        __syncthreads();
    }

    // ---- Epilogue: fp32 H + fp16 shadow ----
#pragma unroll
    for (int mt = 0; mt < 2; ++mt)
#pragma unroll
        for (int nt = 0; nt < 4; ++nt) {
            int row = row0 + m0w + mt * 16 + g;
            int col = n0w + nt * 8 + t * 2;
            if (row < M) {
                *(float2*)(H + (size_t)row * NTOT + col) =
                    make_float2(acc[mt][nt][0], acc[mt][nt][1]);
                *(__half2*)(g_h16 + (size_t)row * NTOT + col) =
                    __floats2half2_rn(acc[mt][nt][0], acc[mt][nt][1]);
            }
            if (row + 8 < M) {
                *(float2*)(H + (size_t)(row + 8) * NTOT + col) =
                    make_float2(acc[mt][nt][2], acc[mt][nt][3]);
                *(__half2*)(g_h16 + (size_t)(row + 8) * NTOT + col) =
                    __floats2half2_rn(acc[mt][nt][2], acc[mt][nt][3]);
            }
        }
}

// ---------------------------------------------------------------------------
// Edge kernel on fp16 shadow: 8 lanes/edge, 4 edges/warp.
// ---------------------------------------------------------------------------
__device__ __forceinline__ float dot8_absdiff(uint4 x, uint4 y,
                                              float4 a0, float4 a1) {
    float2 fx0 = __half22float2(*(__half2*)&x.x), fy0 = __half22float2(*(__half2*)&y.x);
    float2 fx1 = __half22float2(*(__half2*)&x.y), fy1 = __half22float2(*(__half2*)&y.y);
    float2 fx2 = __half22float2(*(__half2*)&x.z), fy2 = __half22float2(*(__half2*)&y.z);
    float2 fx3 = __half22float2(*(__half2*)&x.w), fy3 = __half22float2(*(__half2*)&y.w);
    float s;
    s  = fabsf(fx0.x - fy0.x) * a0.x;
    s += fabsf(fx0.y - fy0.y) * a0.y;
    s += fabsf(fx1.x - fy1.x) * a0.z;
    s += fabsf(fx1.y - fy1.y) * a0.w;
    s += fabsf(fx2.x - fy2.x) * a1.x;
    s += fabsf(fx2.y - fy2.y) * a1.y;
    s += fabsf(fx3.x - fy3.x) * a1.z;
    s += fabsf(fx3.y - fy3.y) * a1.w;
    return s;
}

__global__ __launch_bounds__(256) void sgl_edge_kernel(
    const int* __restrict__ edge,
    const float* __restrict__ a,
    float* __restrict__ out,
    int E)
{
    const int lane = threadIdx.x & 31;
    const int g = lane >> 3;
    const int l = lane & 7;

    float4 aA0 = *(const float4*)(a +      8 * l);
    float4 aA1 = *(const float4*)(a +      8 * l + 4);
    float4 aB0 = *(const float4*)(a + 64 + 8 * l);
    float4 aB1 = *(const float4*)(a + 64 + 8 * l + 4);

    const int warp_id = blockIdx.x * (blockDim.x >> 5) + (threadIdx.x >> 5);
    const int nwarps  = gridDim.x * (blockDim.x >> 5);
    const int nquads  = (E + 3) >> 2;

    for (int quad = warp_id; quad < nquads; quad += nwarps) {
        int e = quad * 4 + g;
        bool valid = e < E;
        int ec = valid ? e : 0;

        int u = edge[ec];
        int v = edge[(size_t)E + ec];

        const uint4* xp = (const uint4*)(g_h16 + (size_t)u * NTOT) + l;
        const uint4* yp = (const uint4*)(g_h16 + (size_t)v * NTOT) + l;

        uint4 x0 = xp[0], x1 = xp[8];
        uint4 y0 = yp[0], y1 = yp[8];

        float s = dot8_absdiff(x0, y0, aA0, aA1)
                + dot8_absdiff(x1, y1, aB0, aB1);

        s += __shfl_xor_sync(0xffffffffu, s, 1);
        s += __shfl_xor_sync(0xffffffffu, s, 2);
        s += __shfl_xor_sync(0xffffffffu, s, 4);

        if (l == 0 && valid) out[e] = fmaxf(s, 0.f);
    }
}

extern "C" void kernel_launch(void* const* d_in, const int* in_sizes, int n_in,
                              void* d_out, int out_size)
{
    const float* A    = (const float*)d_in[0];
    const int*   edge = (const int*)d_in[1];
    const float* W    = (const float*)d_in[2];
    const float* a    = (const float*)d_in[3];

    const int M = in_sizes[0] / KTOT;
    const int E = in_sizes[1] / 2;

    float* H  = (float*)d_out;
    float* ew = (float*)d_out + (size_t)M * NTOT;

    cudaFuncSetAttribute(sgl_gemm_mma,
                         cudaFuncAttributeMaxDynamicSharedMemorySize, S_TOTAL);

    prep_w<<<128, 256>>>(W);

    int gemm_blocks = (M + MTILE - 1) / MTILE;
    sgl_gemm_mma<<<gemm_blocks, 512, S_TOTAL>>>(A, H, M);

    int edge_blocks = 2048;
    sgl_edge_kernel<<<edge_blocks, 256>>>(edge, a, ew, E);
}